// round 1
// baseline (speedup 1.0000x reference)
#include <cuda_runtime.h>

// Problem shape (fixed by the dataset): B=4, S=4096, D=2048, W=4
#define BV 4
#define SV 4096
#define DV 2048

// Scratch (no allocations allowed) ------------------------------------------
__device__ float g_rinv[BV * SV];
__device__ int   g_mask[BV * SV];
__device__ int   g_src [BV * SV];

// K0: rinv[b,s] = rsqrt(mean(x^2) + 1e-5). One warp per token. --------------
__global__ void __launch_bounds__(256) rinv_kernel(const float* __restrict__ x) {
    int gw   = (blockIdx.x * blockDim.x + threadIdx.x) >> 5;
    int lane = threadIdx.x & 31;
    if (gw >= BV * SV) return;
    const float4* xr = (const float4*)(x + (size_t)gw * DV);
    float s = 0.f;
#pragma unroll
    for (int i = 0; i < 16; i++) {
        float4 v = xr[lane + i * 32];
        s += v.x * v.x + v.y * v.y + v.z * v.z + v.w * v.w;
    }
#pragma unroll
    for (int o = 16; o > 0; o >>= 1) s += __shfl_xor_sync(0xffffffffu, s, o);
    if (lane == 0) g_rinv[gw] = rsqrtf(s * (1.f / DV) + 1e-5f);
}

// K1: fused rmsnorm-scale + causal depthwise conv(W=4) + silu + (p1-p0) dot.
// Tile of 32 tokens per block; ring accumulators so each x row is read once.
// s0 % 4 == 0, so ring slot indices depend only on compile-time k/j.
__global__ void __launch_bounds__(256) score_kernel(
    const float* __restrict__ x, const float* __restrict__ nw,
    const float* __restrict__ cw, const float* __restrict__ pw)
{
    const int b   = blockIdx.y;
    const int s0  = blockIdx.x * 32;
    const int tid = threadIdx.x;
    const int c0  = tid * 8;

    __shared__ float scores[32];
    if (tid < 32) scores[tid] = 0.f;
    __syncthreads();

    // Per-channel constants in registers
    float wv[4][8], g[8], nv[8];
#pragma unroll
    for (int c = 0; c < 8; c++) {
        int d = c0 + c;
        nv[c] = nw[d];
        g[c]  = pw[DV + d] - pw[d];   // p1 - p0
#pragma unroll
        for (int wi = 0; wi < 4; wi++) wv[wi][c] = cw[d * 4 + wi];
    }

    float acc[4][8];
#pragma unroll
    for (int s = 0; s < 4; s++)
#pragma unroll
        for (int c = 0; c < 8; c++) acc[s][c] = 0.f;

    const float* xb = x + (size_t)b * SV * DV + c0;
    const float* rb = g_rinv + b * SV;

    // rows i = 0..34 map to global rows r = s0-3+i ; i=35 is padding
    for (int base = 0; base < 36; base += 4) {
#pragma unroll
        for (int k = 0; k < 4; k++) {
            const int i = base + k;
            const int r = s0 - 3 + i;
            float h[8];
            if (i < 35 && r >= 0) {
                float ri = rb[r];
                const float4* xr = (const float4*)(xb + (size_t)r * DV);
                float4 a = xr[0], q = xr[1];
                h[0] = a.x * ri * nv[0]; h[1] = a.y * ri * nv[1];
                h[2] = a.z * ri * nv[2]; h[3] = a.w * ri * nv[3];
                h[4] = q.x * ri * nv[4]; h[5] = q.y * ri * nv[5];
                h[6] = q.z * ri * nv[6]; h[7] = q.w * ri * nv[7];
            } else {
#pragma unroll
                for (int c = 0; c < 8; c++) h[c] = 0.f;
            }
            // row r contributes conv[3-j] to token r+j  (slots compile-time)
#pragma unroll
            for (int j = 0; j < 4; j++) {
                const int slot = (k + 1 + j) & 3;
#pragma unroll
                for (int c = 0; c < 8; c++) acc[slot][c] += wv[3 - j][c] * h[c];
            }
            // token r complete after its own row: silu + gate-dot + reduce
            if (i >= 3 && i < 35) {
                const int slot = (k + 1) & 3;
                float p = 0.f;
#pragma unroll
                for (int c = 0; c < 8; c++) {
                    float v = acc[slot][c];
                    float e = __expf(-v);
                    p += g[c] * __fdividef(v, 1.f + e);
                }
#pragma unroll
                for (int o = 16; o > 0; o >>= 1)
                    p += __shfl_xor_sync(0xffffffffu, p, o);
                if ((tid & 31) == 0) atomicAdd(&scores[i - 3], p);
            }
            {   // recycle slot for token r+4
                const int slot = (k + 1) & 3;
#pragma unroll
                for (int c = 0; c < 8; c++) acc[slot][c] = 0.f;
            }
        }
    }
    __syncthreads();
    if (tid < 32) g_mask[b * SV + s0 + tid] = (scores[tid] > 0.f) ? 1 : 0;
}

// K2: per-batch inclusive scan of masks -> inverse map src[b][c-1] = s -------
__global__ void __launch_bounds__(1024) scan_kernel() {
    const int b   = blockIdx.x;
    const int tid = threadIdx.x;
    for (int j = tid; j < SV; j += 1024) g_src[b * SV + j] = -1;
    __syncthreads();

    int base = tid * 4;
    int m[4], pre[4];
    int sum = 0;
#pragma unroll
    for (int k = 0; k < 4; k++) {
        m[k] = g_mask[b * SV + base + k];
        sum += m[k];
        pre[k] = sum;
    }
    int lane = tid & 31, wid = tid >> 5;
    int v = sum;
#pragma unroll
    for (int o = 1; o < 32; o <<= 1) {
        int t = __shfl_up_sync(0xffffffffu, v, o);
        if (lane >= o) v += t;
    }
    __shared__ int wsum[32];
    if (lane == 31) wsum[wid] = v;
    __syncthreads();
    if (wid == 0) {
        int t = wsum[lane];
#pragma unroll
        for (int o = 1; o < 32; o <<= 1) {
            int u = __shfl_up_sync(0xffffffffu, t, o);
            if (lane >= o) t += u;
        }
        wsum[lane] = t;
    }
    __syncthreads();
    int offset = (wid > 0 ? wsum[wid - 1] : 0) + (v - sum);
#pragma unroll
    for (int k = 0; k < 4; k++) {
        if (m[k]) g_src[b * SV + offset + pre[k] - 1] = base + k;
    }
}

// K3: row-wise gather of x (selected, packed) or zero-fill -------------------
__global__ void __launch_bounds__(256) scatter_kernel(
    const float* __restrict__ x, float* __restrict__ out)
{
    const int row = blockIdx.x;              // 0 .. B*S-1
    const int b   = row >> 12;               // S = 4096
    const int s   = g_src[row];
    float4* o = (float4*)(out + (size_t)row * DV) + threadIdx.x;
    if (s >= 0) {
        const float4* xr =
            (const float4*)(x + ((size_t)(b << 12) + s) * DV) + threadIdx.x;
        o[0]   = xr[0];
        o[256] = xr[256];
    } else {
        float4 z = make_float4(0.f, 0.f, 0.f, 0.f);
        o[0]   = z;
        o[256] = z;
    }
}

extern "C" void kernel_launch(void* const* d_in, const int* in_sizes, int n_in,
                              void* d_out, int out_size) {
    const float* x  = (const float*)d_in[0];  // [B,S,D]
    const float* nw = (const float*)d_in[1];  // [D]
    const float* cw = (const float*)d_in[2];  // [D,4]
    const float* pw = (const float*)d_in[3];  // [2,D]
    float* out = (float*)d_out;               // [B,S,D]

    rinv_kernel<<<(BV * SV) / 8, 256>>>(x);
    dim3 g1(SV / 32, BV);
    score_kernel<<<g1, 256>>>(x, nw, cw, pw);
    scan_kernel<<<BV, 1024>>>();
    scatter_kernel<<<BV * SV, 256>>>(x, out);
}

// round 2
// speedup vs baseline: 1.3784x; 1.3784x over previous
#include <cuda_runtime.h>

// Problem shape (fixed by the dataset): B=4, S=4096, D=2048, W=4
#define BV 4
#define SV 4096
#define DV 2048

// Scratch (no allocations allowed) ------------------------------------------
__device__ int g_mask[BV * SV];
__device__ int g_src [BV * SV];

// Packed f32x2 helpers (FFMA2 — ptxas never emits these from C++) ------------
typedef unsigned long long u64;
static __device__ __forceinline__ u64 pk(float lo, float hi) {
    u64 r; asm("mov.b64 %0,{%1,%2};" : "=l"(r) : "f"(lo), "f"(hi)); return r;
}
static __device__ __forceinline__ void upk(u64 v, float& lo, float& hi) {
    asm("mov.b64 {%0,%1},%2;" : "=f"(lo), "=f"(hi) : "l"(v));
}
static __device__ __forceinline__ u64 f2fma(u64 a, u64 b, u64 c) {
    u64 d; asm("fma.rn.f32x2 %0,%1,%2,%3;" : "=l"(d) : "l"(a), "l"(b), "l"(c)); return d;
}
static __device__ __forceinline__ u64 f2mul(u64 a, u64 b) {
    u64 d; asm("mul.rn.f32x2 %0,%1,%2;" : "=l"(d) : "l"(a), "l"(b)); return d;
}

// K1: fused rmsnorm (in-block reduce) + causal dwconv(W=4) + silu + (p1-p0)
// dot -> sign per token. 32 tokens per block, ring accumulators, 1-row
// prefetch to hide DRAM latency, packed f32x2 for the conv FMAs.
__global__ void __launch_bounds__(256, 2) score_kernel(
    const float* __restrict__ x, const float* __restrict__ nw,
    const float* __restrict__ cw, const float* __restrict__ pw)
{
    const int b    = blockIdx.y;
    const int s0   = blockIdx.x * 32;
    const int tid  = threadIdx.x;
    const int lane = tid & 31, wid = tid >> 5;
    const int c0   = tid * 8;

    __shared__ float wpart[2][8];    // per-row sumsq warp partials (dbl-buf)
    __shared__ float spart[32][8];   // per-token score warp partials

    // Per-channel constants (packed pairs)
    u64 nv2[4], wv2[4][4];
    float gch[8];
#pragma unroll
    for (int j = 0; j < 4; j++) {
        int d = c0 + 2 * j;
        nv2[j] = pk(nw[d], nw[d + 1]);
#pragma unroll
        for (int wi = 0; wi < 4; wi++)
            wv2[wi][j] = pk(cw[d * 4 + wi], cw[(d + 1) * 4 + wi]);
    }
#pragma unroll
    for (int c = 0; c < 8; c++) {
        int d = c0 + c;
        gch[c] = pw[DV + d] - pw[d];   // p1 - p0
    }

    u64 acc2[4][4];
#pragma unroll
    for (int s = 0; s < 4; s++)
#pragma unroll
        for (int j = 0; j < 4; j++) acc2[s][j] = 0ull;

    const float* xb = x + (size_t)b * SV * DV + c0;

    // Prologue: prefetch row for i = 0 (global row s0-3)
    float4 pa, pq;
    {
        int r = s0 - 3;
        if (r >= 0) {
            const float4* xr = (const float4*)(xb + (size_t)r * DV);
            pa = xr[0]; pq = xr[1];
        } else {
            pa = make_float4(0.f, 0.f, 0.f, 0.f); pq = pa;
        }
    }

    // rows i = 0..34 -> global rows r = s0-3+i ; i = 35 is flush padding
    for (int base = 0; base < 36; base += 4) {
#pragma unroll
        for (int k = 0; k < 4; k++) {
            const int i = base + k;
            const int r = s0 - 3 + i;

            float4 a = pa, q = pq;
            // Prefetch row i+1 (hides DRAM latency behind this row's work)
            {
                const int rn = r + 1;
                if (i + 1 < 35 && rn >= 0) {
                    const float4* xr = (const float4*)(xb + (size_t)rn * DV);
                    pa = xr[0]; pq = xr[1];
                } else {
                    pa = make_float4(0.f, 0.f, 0.f, 0.f); pq = pa;
                }
            }

            // Pack this row's 8 values
            u64 x2[4] = { pk(a.x, a.y), pk(a.z, a.w),
                          pk(q.x, q.y), pk(q.z, q.w) };

            // Block-wide sum of squares -> rinv for this row (deterministic)
            u64 ss = 0ull;
#pragma unroll
            for (int j = 0; j < 4; j++) ss = f2fma(x2[j], x2[j], ss);
            float slo, shi; upk(ss, slo, shi);
            float part = slo + shi;
#pragma unroll
            for (int o = 16; o > 0; o >>= 1)
                part += __shfl_xor_sync(0xffffffffu, part, o);
            const int par = i & 1;
            if (lane == 0) wpart[par][wid] = part;
            __syncthreads();
            float tot = 0.f;
#pragma unroll
            for (int w = 0; w < 8; w++) tot += wpart[par][w];
            const float ri = rsqrtf(tot * (1.f / DV) + 1e-5f);

            // h = x * rinv * norm_weight (packed)
            const u64 ri2 = pk(ri, ri);
            u64 h2[4];
#pragma unroll
            for (int j = 0; j < 4; j++)
                h2[j] = f2mul(f2mul(ri2, nv2[j]), x2[j]);

            // row r contributes conv tap [3-jj] to token r+jj
#pragma unroll
            for (int jj = 0; jj < 4; jj++) {
                const int slot = (k + 1 + jj) & 3;
#pragma unroll
                for (int j = 0; j < 4; j++)
                    acc2[slot][j] = f2fma(wv2[3 - jj][j], h2[j], acc2[slot][j]);
            }

            // Token r complete after its own row: silu + gate-dot + reduce
            if (i >= 3 && i < 35) {
                const int slot = (k + 1) & 3;
                float p = 0.f;
#pragma unroll
                for (int j = 0; j < 4; j++) {
                    float v0, v1; upk(acc2[slot][j], v0, v1);
                    p += gch[2 * j]     * __fdividef(v0, 1.f + __expf(-v0));
                    p += gch[2 * j + 1] * __fdividef(v1, 1.f + __expf(-v1));
                }
#pragma unroll
                for (int o = 16; o > 0; o >>= 1)
                    p += __shfl_xor_sync(0xffffffffu, p, o);
                if (lane == 0) spart[i - 3][wid] = p;
            }
            // Recycle slot for token r+4
            {
                const int slot = (k + 1) & 3;
#pragma unroll
                for (int j = 0; j < 4; j++) acc2[slot][j] = 0ull;
            }
        }
    }
    __syncthreads();
    if (tid < 32) {
        float t = 0.f;
#pragma unroll
        for (int w = 0; w < 8; w++) t += spart[tid][w];
        g_mask[b * SV + s0 + tid] = (t > 0.f) ? 1 : 0;
    }
}

// K2: per-batch inclusive scan of masks -> inverse map src[b][c-1] = s -------
__global__ void __launch_bounds__(1024) scan_kernel() {
    const int b   = blockIdx.x;
    const int tid = threadIdx.x;
    for (int j = tid; j < SV; j += 1024) g_src[b * SV + j] = -1;
    __syncthreads();

    int base = tid * 4;
    int m[4], pre[4];
    int sum = 0;
#pragma unroll
    for (int k = 0; k < 4; k++) {
        m[k] = g_mask[b * SV + base + k];
        sum += m[k];
        pre[k] = sum;
    }
    int lane = tid & 31, wid = tid >> 5;
    int v = sum;
#pragma unroll
    for (int o = 1; o < 32; o <<= 1) {
        int t = __shfl_up_sync(0xffffffffu, v, o);
        if (lane >= o) v += t;
    }
    __shared__ int wsum[32];
    if (lane == 31) wsum[wid] = v;
    __syncthreads();
    if (wid == 0) {
        int t = wsum[lane];
#pragma unroll
        for (int o = 1; o < 32; o <<= 1) {
            int u = __shfl_up_sync(0xffffffffu, t, o);
            if (lane >= o) t += u;
        }
        wsum[lane] = t;
    }
    __syncthreads();
    int offset = (wid > 0 ? wsum[wid - 1] : 0) + (v - sum);
#pragma unroll
    for (int k = 0; k < 4; k++) {
        if (m[k]) g_src[b * SV + offset + pre[k] - 1] = base + k;
    }
}

// K3: row-wise gather of x (selected, packed) or zero-fill -------------------
__global__ void __launch_bounds__(256) scatter_kernel(
    const float* __restrict__ x, float* __restrict__ out)
{
    const int row = blockIdx.x;              // 0 .. B*S-1
    const int b   = row >> 12;               // S = 4096
    const int s   = g_src[row];
    float4* o = (float4*)(out + (size_t)row * DV) + threadIdx.x;
    if (s >= 0) {
        const float4* xr =
            (const float4*)(x + ((size_t)(b << 12) + s) * DV) + threadIdx.x;
        float4 v0 = __ldcs(xr);
        float4 v1 = __ldcs(xr + 256);
        __stcs(o, v0);
        __stcs(o + 256, v1);
    } else {
        float4 z = make_float4(0.f, 0.f, 0.f, 0.f);
        __stcs(o, z);
        __stcs(o + 256, z);
    }
}

extern "C" void kernel_launch(void* const* d_in, const int* in_sizes, int n_in,
                              void* d_out, int out_size) {
    const float* x  = (const float*)d_in[0];  // [B,S,D]
    const float* nw = (const float*)d_in[1];  // [D]
    const float* cw = (const float*)d_in[2];  // [D,4]
    const float* pw = (const float*)d_in[3];  // [2,D]
    float* out = (float*)d_out;               // [B,S,D]

    dim3 g1(SV / 32, BV);
    score_kernel<<<g1, 256>>>(x, nw, cw, pw);
    scan_kernel<<<BV, 1024>>>();
    scatter_kernel<<<BV * SV, 256>>>(x, out);
}